// round 4
// baseline (speedup 1.0000x reference)
#include <cuda_runtime.h>
#include <cuda_bf16.h>
#include <cstdint>

// DiffUnpool: out[b] = S[b] @ x[b]
//   S: [16, 2048, 256] f32   x: [16, 256, 256] f32   out: [16, 2048, 256] f32
// bf16 hi/lo split on mma.sync.m16n8k16: D = Shi*Xhi + Shi*Xlo + Slo*Xhi.
// A fragments loaded DIRECTLY from global (coalesced float2 per quad) and
// split in registers -> no A smem traffic. B via double-buffered smem +
// ldmatrix.trans (one syncthreads per K-chunk).

#define BM 128
#define BN 64
#define BK 32
#define B_STRIDE 128            // bytes per B smem row (64 bf16)
#define BUF 4096                // one B buffer (32 rows * 128B)
// smem: [buf0 hi][buf0 lo][buf1 hi][buf1 lo]
#define SM_TOTAL (4 * BUF)

static __device__ __forceinline__ uint32_t cvta_smem(const void* p) {
    uint32_t a;
    asm("{ .reg .u64 t; cvta.to.shared.u64 t, %1; cvt.u32.u64 %0, t; }"
        : "=r"(a) : "l"(p));
    return a;
}

#define LDSM_X4_T(r0, r1, r2, r3, a) \
    asm volatile("ldmatrix.sync.aligned.m8n8.x4.trans.shared.b16 {%0,%1,%2,%3}, [%4];" \
                 : "=r"(r0), "=r"(r1), "=r"(r2), "=r"(r3) : "r"(a))
#define MMA16816(d, a, b0, b1) \
    asm volatile("mma.sync.aligned.m16n8k16.row.col.f32.bf16.bf16.f32 " \
                 "{%0,%1,%2,%3},{%4,%5,%6,%7},{%8,%9},{%0,%1,%2,%3};" \
                 : "+f"((d)[0]), "+f"((d)[1]), "+f"((d)[2]), "+f"((d)[3]) \
                 : "r"((a)[0]), "r"((a)[1]), "r"((a)[2]), "r"((a)[3]), "r"(b0), "r"(b1))

static __device__ __forceinline__ void split2(float v0, float v1, uint32_t& hi, uint32_t& lo) {
    __nv_bfloat16 h0 = __float2bfloat16(v0);
    __nv_bfloat16 h1 = __float2bfloat16(v1);
    __nv_bfloat16 l0 = __float2bfloat16(v0 - __bfloat162float(h0));
    __nv_bfloat16 l1 = __float2bfloat16(v1 - __bfloat162float(h1));
    hi = (uint32_t)__bfloat16_as_ushort(h0) | ((uint32_t)__bfloat16_as_ushort(h1) << 16);
    lo = (uint32_t)__bfloat16_as_ushort(l0) | ((uint32_t)__bfloat16_as_ushort(l1) << 16);
}

__global__ __launch_bounds__(256, 2)
void diffunpool_hmma2(const float* __restrict__ S, const float* __restrict__ X,
                      float* __restrict__ O) {
    __shared__ __align__(16) char smem[SM_TOTAL];

    const int nt = blockIdx.x;       // 0..3
    const int mt = blockIdx.y;       // 0..15
    const int b  = blockIdx.z;       // 0..15

    const float* Sb = S + ((size_t)b * 2048 + (size_t)mt * BM) * 256;
    const float* Xb = X + (size_t)b * 256 * 256 + (size_t)nt * BN;
    float*       Ob = O + ((size_t)b * 2048 + (size_t)mt * BM) * 256 + (size_t)nt * BN;

    const int tid  = threadIdx.x;
    const int wid  = tid >> 5;
    const int lane = tid & 31;
    const int warp_m = (wid & 3) * 32;
    const int warp_n = (wid >> 2) * 32;
    const uint32_t sb = cvta_smem(smem);

    // ---- B global load + smem store mapping (one 8-float group per thread)
    const int brow = tid >> 3;              // k row within chunk: 0..31
    const int bch  = tid & 7;               // 16B chunk within 128B row
    const float* pB = Xb + (size_t)brow * 256 + bch * 8;
    const uint32_t b_sts = (uint32_t)brow * B_STRIDE + (uint32_t)((bch ^ (brow & 7)) << 4);

    // ---- A fragment lane mapping (direct global loads)
    const int fr = lane >> 2;               // fragment row 0..7
    const int fc = (lane & 3) * 2;          // fragment col pair base
    const float* pA = Sb + (size_t)(warp_m + fr) * 256 + fc;

    // ---- B ldmatrix lane mapping (validated in R3)
    const uint32_t b_lrow = (uint32_t)(lane & 15);
    const uint32_t b_lc   = (uint32_t)((warp_n >> 3) + (lane >> 4));

    float d[2][4][4];
#pragma unroll
    for (int i = 0; i < 2; i++)
#pragma unroll
        for (int j = 0; j < 4; j++)
#pragma unroll
            for (int r = 0; r < 4; r++) d[i][j][r] = 0.0f;

    float4 rB0 = *(const float4*)pB;
    float4 rB1 = *(const float4*)(pB + 4);

    for (int c = 0; c < 8; c++) {
        // ---- A globals for chunk c: issue LDGs early (before the barrier)
        float2 fa[2][2][4];  // [kk][i][reg]
#pragma unroll
        for (int i = 0; i < 2; i++)
#pragma unroll
            for (int kk = 0; kk < 2; kk++) {
                const float* base = pA + (size_t)(i * 16) * 256 + c * BK + kk * 16;
                fa[kk][i][0] = *(const float2*)(base);
                fa[kk][i][1] = *(const float2*)(base + 8 * 256);
                fa[kk][i][2] = *(const float2*)(base + 8);
                fa[kk][i][3] = *(const float2*)(base + 8 * 256 + 8);
            }

        // ---- convert + store B chunk c into buffer c&1
        const uint32_t bufbase = (uint32_t)(c & 1) * (2 * BUF);
        {
            uint32_t h[4], l[4];
            split2(rB0.x, rB0.y, h[0], l[0]);
            split2(rB0.z, rB0.w, h[1], l[1]);
            split2(rB1.x, rB1.y, h[2], l[2]);
            split2(rB1.z, rB1.w, h[3], l[3]);
            *(uint4*)(smem + bufbase + b_sts)       = make_uint4(h[0], h[1], h[2], h[3]);
            *(uint4*)(smem + bufbase + BUF + b_sts) = make_uint4(l[0], l[1], l[2], l[3]);
        }
        __syncthreads();

        // ---- prefetch B chunk c+1
        if (c < 7) {
            const float* p = pB + (size_t)(c + 1) * BK * 256;
            rB0 = *(const float4*)p;
            rB1 = *(const float4*)(p + 4);
        }

        // ---- split A fragments in registers
        uint32_t ah[2][2][4], al[2][2][4];
#pragma unroll
        for (int kk = 0; kk < 2; kk++)
#pragma unroll
            for (int i = 0; i < 2; i++)
#pragma unroll
                for (int r = 0; r < 4; r++)
                    split2(fa[kk][i][r].x, fa[kk][i][r].y, ah[kk][i][r], al[kk][i][r]);

        // ---- compute
#pragma unroll
        for (int kk = 0; kk < 2; kk++) {
            uint32_t bh[2][4], bl[2][4];
#pragma unroll
            for (int nb = 0; nb < 2; nb++) {
                uint32_t row  = (uint32_t)(kk * 16) + b_lrow;
                uint32_t ch   = (b_lc + nb * 2) ^ (row & 7);
                uint32_t addr = sb + bufbase + row * B_STRIDE + (ch << 4);
                LDSM_X4_T(bh[nb][0], bh[nb][1], bh[nb][2], bh[nb][3], addr);
                LDSM_X4_T(bl[nb][0], bl[nb][1], bl[nb][2], bl[nb][3], addr + BUF);
            }
#pragma unroll
            for (int i = 0; i < 2; i++)
#pragma unroll
                for (int nb = 0; nb < 2; nb++) {
                    MMA16816(d[i][2*nb],   ah[kk][i], bh[nb][0], bh[nb][1]);   // Shi*Xhi
                    MMA16816(d[i][2*nb+1], ah[kk][i], bh[nb][2], bh[nb][3]);
                    MMA16816(d[i][2*nb],   ah[kk][i], bl[nb][0], bl[nb][1]);   // Shi*Xlo
                    MMA16816(d[i][2*nb+1], ah[kk][i], bl[nb][2], bl[nb][3]);
                    MMA16816(d[i][2*nb],   al[kk][i], bh[nb][0], bh[nb][1]);   // Slo*Xhi
                    MMA16816(d[i][2*nb+1], al[kk][i], bh[nb][2], bh[nb][3]);
                }
        }
        // no second barrier: next iteration writes the other buffer
    }

    // ---- epilogue (same mapping as R3)
    const int group = lane >> 2;
    const int tcol  = (lane & 3) * 2;
#pragma unroll
    for (int i = 0; i < 2; i++) {
        int m0 = warp_m + i * 16 + group;
#pragma unroll
        for (int j = 0; j < 4; j++) {
            int n0 = warp_n + j * 8 + tcol;
            *(float2*)(Ob + (size_t)m0 * 256 + n0)       = make_float2(d[i][j][0], d[i][j][1]);
            *(float2*)(Ob + (size_t)(m0 + 8) * 256 + n0) = make_float2(d[i][j][2], d[i][j][3]);
        }
    }
}

extern "C" void kernel_launch(void* const* d_in, const int* in_sizes, int n_in,
                              void* d_out, int out_size) {
    const float* S = nullptr;
    const float* X = nullptr;
    for (int i = 0; i < n_in; i++) {
        if (in_sizes[i] == 8388608)      S = (const float*)d_in[i];
        else if (in_sizes[i] == 1048576) X = (const float*)d_in[i];
    }
    float* O = (float*)d_out;

    dim3 grid(256 / BN, 2048 / BM, 16);   // (4, 16, 16)
    diffunpool_hmma2<<<grid, 256>>>(S, X, O);
}

// round 5
// speedup vs baseline: 1.3049x; 1.3049x over previous
#include <cuda_runtime.h>
#include <cstdint>

// DiffUnpool: out[b] = S[b] @ x[b]
//   S: [16, 2048, 256] f32   x: [16, 256, 256] f32   out: [16, 2048, 256] f32
// Single-product tf32 mma.sync.m16n8k8 (cvt.rna), fp32 accumulate.
// fp32 smem, stride-36 padding (bank = 4*row + col : conflict-free everywhere),
// double-buffered A and B, one __syncthreads per K-chunk.

#define BM 128
#define BN 64
#define BK 32
#define ASTR 36
#define A_BUF (128 * ASTR)            // floats per A buffer (4608)
#define B_BUF (64 * ASTR)             // floats per B buffer (2304)
#define SM_BYTES ((2 * A_BUF + 2 * B_BUF) * 4)   // 55296

static __device__ __forceinline__ uint32_t tf32c(float f) {
    uint32_t u;
    asm("cvt.rna.tf32.f32 %0, %1;" : "=r"(u) : "f"(f));
    return u;
}
static __device__ __forceinline__ uint32_t fbits(float f) { return __float_as_uint(f); }

#define MMA_TF32(d, a, b0, b1) \
    asm volatile("mma.sync.aligned.m16n8k8.row.col.f32.tf32.tf32.f32 " \
                 "{%0,%1,%2,%3},{%4,%5,%6,%7},{%8,%9},{%0,%1,%2,%3};" \
                 : "+f"((d)[0]), "+f"((d)[1]), "+f"((d)[2]), "+f"((d)[3]) \
                 : "r"((a)[0]), "r"((a)[1]), "r"((a)[2]), "r"((a)[3]), "r"(b0), "r"(b1))

extern __shared__ float sm[];

__global__ __launch_bounds__(256, 2)
void diffunpool_tf32(const float* __restrict__ S, const float* __restrict__ X,
                     float* __restrict__ O) {
    const int nt = blockIdx.x;       // 0..3
    const int mt = blockIdx.y;       // 0..15
    const int b  = blockIdx.z;       // 0..15

    const float* Sb = S + ((size_t)b * 2048 + (size_t)mt * BM) * 256;
    const float* Xb = X + (size_t)b * 256 * 256 + (size_t)nt * BN;
    float*       Ob = O + ((size_t)b * 2048 + (size_t)mt * BM) * 256 + (size_t)nt * BN;

    const int tid  = threadIdx.x;
    const int wid  = tid >> 5;
    const int lane = tid & 31;
    const int warp_m = (wid & 3) * 32;
    const int warp_n = (wid >> 2) * 32;

    // ---- global load mappings
    const int arow = tid >> 1, acol = (tid & 1) * 16;       // A: 16 floats/thread/chunk
    const float* pA = Sb + (size_t)arow * 256 + acol;
    const int bn = tid & 63, bkq = tid >> 6;                // B: 8 floats/thread/chunk
    const float* pB = Xb + (size_t)(bkq * 8) * 256 + bn;

    // ---- smem store bases
    float* Abase = sm;                     // [2][128][ASTR]
    float* Bbase = sm + 2 * A_BUF;         // [2][64][ASTR]
    uint32_t* AstA = (uint32_t*)(Abase) + arow * ASTR + acol;
    uint32_t* BstB = (uint32_t*)(Bbase) + bn * ASTR + bkq * 8;

    // ---- fragment read mappings (bank = 4*row + col, conflict-free)
    const int fr = lane >> 2, fc = lane & 3;
    const float* aF = Abase + (warp_m + fr) * ASTR + fc;
    const float* bF = Bbase + (warp_n + fr) * ASTR + fc;

    float d[2][4][4];
#pragma unroll
    for (int i = 0; i < 2; i++)
#pragma unroll
        for (int j = 0; j < 4; j++)
#pragma unroll
            for (int r = 0; r < 4; r++) d[i][j][r] = 0.0f;

    // ---- prologue: chunk 0 globals
    float4 rA[4];
    float rB[8];
#pragma unroll
    for (int q = 0; q < 4; q++) rA[q] = *(const float4*)(pA + q * 4);
#pragma unroll
    for (int j = 0; j < 8; j++) rB[j] = pB[(size_t)j * 256];

    for (int c = 0; c < 8; c++) {
        const int buf = c & 1;
        // ---- convert + store chunk c
        uint32_t* As = AstA + buf * A_BUF;
#pragma unroll
        for (int q = 0; q < 4; q++) {
            uint4 v = make_uint4(tf32c(rA[q].x), tf32c(rA[q].y),
                                 tf32c(rA[q].z), tf32c(rA[q].w));
            *(uint4*)(As + q * 4) = v;
        }
        uint32_t* Bs = BstB + buf * B_BUF;
        {
            uint4 v0 = make_uint4(tf32c(rB[0]), tf32c(rB[1]), tf32c(rB[2]), tf32c(rB[3]));
            uint4 v1 = make_uint4(tf32c(rB[4]), tf32c(rB[5]), tf32c(rB[6]), tf32c(rB[7]));
            *(uint4*)(Bs)     = v0;
            *(uint4*)(Bs + 4) = v1;
        }
        __syncthreads();

        // ---- prefetch chunk c+1 globals (hidden under compute)
        if (c < 7) {
            const float* nA = pA + (c + 1) * BK;
#pragma unroll
            for (int q = 0; q < 4; q++) rA[q] = *(const float4*)(nA + q * 4);
            const float* nB = pB + (size_t)(c + 1) * BK * 256;
#pragma unroll
            for (int j = 0; j < 8; j++) rB[j] = nB[(size_t)j * 256];
        }

        // ---- compute chunk c
        const float* Af = aF + buf * A_BUF;
        const float* Bf = bF + buf * B_BUF;
#pragma unroll
        for (int kk = 0; kk < 4; kk++) {
            uint32_t a[2][4];
#pragma unroll
            for (int i = 0; i < 2; i++) {
                const float* p = Af + i * 16 * ASTR + kk * 8;
                a[i][0] = fbits(p[0]);
                a[i][1] = fbits(p[8 * ASTR]);
                a[i][2] = fbits(p[4]);
                a[i][3] = fbits(p[8 * ASTR + 4]);
            }
#pragma unroll
            for (int j = 0; j < 4; j++) {
                const float* q = Bf + j * 8 * ASTR + kk * 8;
                uint32_t b0 = fbits(q[0]);
                uint32_t b1 = fbits(q[4]);
                MMA_TF32(d[0][j], a[0], b0, b1);
                MMA_TF32(d[1][j], a[1], b0, b1);
            }
        }
        // no trailing barrier: the next iteration's __syncthreads (after STS to
        // the other buffer) orders compute(c) before STS(c+2) reuses this buffer.
    }

    // ---- epilogue
    const int group = lane >> 2;
    const int tcol  = (lane & 3) * 2;
#pragma unroll
    for (int i = 0; i < 2; i++) {
        int m0 = warp_m + i * 16 + group;
#pragma unroll
        for (int j = 0; j < 4; j++) {
            int n0 = warp_n + j * 8 + tcol;
            *(float2*)(Ob + (size_t)m0 * 256 + n0)       = make_float2(d[i][j][0], d[i][j][1]);
            *(float2*)(Ob + (size_t)(m0 + 8) * 256 + n0) = make_float2(d[i][j][2], d[i][j][3]);
        }
    }
}

extern "C" void kernel_launch(void* const* d_in, const int* in_sizes, int n_in,
                              void* d_out, int out_size) {
    const float* S = nullptr;
    const float* X = nullptr;
    for (int i = 0; i < n_in; i++) {
        if (in_sizes[i] == 8388608)      S = (const float*)d_in[i];
        else if (in_sizes[i] == 1048576) X = (const float*)d_in[i];
    }
    float* O = (float*)d_out;

    cudaFuncSetAttribute(diffunpool_tf32,
                         cudaFuncAttributeMaxDynamicSharedMemorySize, SM_BYTES);
    dim3 grid(256 / BN, 2048 / BM, 16);   // (4, 16, 16)
    diffunpool_tf32<<<grid, 256, SM_BYTES>>>(S, X, O);
}

// round 6
// speedup vs baseline: 1.9721x; 1.5113x over previous
#include <cuda_runtime.h>
#include <cstdint>

// DiffUnpool: out[b] = S[b] @ x[b]
//   S: [16, 2048, 256] f32   x: [16, 256, 256] f32   out: [16, 2048, 256] f32
// tf32 m16n8k8 (cvt.rna post-LDS), CTA 128x128, 4 warps of 64x64.
// cp.async double-buffered fp32 staging; A frags via ldmatrix (b16-pair trick,
// XOR-swizzled rows); B frags scalar LDS from stride-544 k-major layout
// (bank = (8k+n)%32, conflict-free for the fragment pattern).

#define A_CHUNK_BYTES 16384          // 128 rows x 128B
#define B_ROWB 544                   // 128 floats + 32B pad
#define B_CHUNK_BYTES (32 * B_ROWB)  // 17408
#define OFF_B (2 * A_CHUNK_BYTES)
#define SM_BYTES (2 * A_CHUNK_BYTES + 2 * B_CHUNK_BYTES)  // 67584

static __device__ __forceinline__ uint32_t cvta_smem(const void* p) {
    uint32_t a;
    asm("{ .reg .u64 t; cvta.to.shared.u64 t, %1; cvt.u32.u64 %0, t; }"
        : "=r"(a) : "l"(p));
    return a;
}
static __device__ __forceinline__ uint32_t tf32c(float f) {
    uint32_t u;
    asm("cvt.rna.tf32.f32 %0, %1;" : "=r"(u) : "f"(f));
    return u;
}

#define CP16(dst, src) \
    asm volatile("cp.async.cg.shared.global [%0], [%1], 16;" :: "r"(dst), "l"(src))
#define CPCOMMIT() asm volatile("cp.async.commit_group;" ::: "memory")
#define CPWAIT1()  asm volatile("cp.async.wait_group 1;" ::: "memory")

#define LDSM4(r0, r1, r2, r3, a) \
    asm volatile("ldmatrix.sync.aligned.m8n8.x4.shared.b16 {%0,%1,%2,%3}, [%4];" \
                 : "=r"(r0), "=r"(r1), "=r"(r2), "=r"(r3) : "r"(a))

#define MMA(d, a, b0, b1) \
    asm volatile("mma.sync.aligned.m16n8k8.row.col.f32.tf32.tf32.f32 " \
                 "{%0,%1,%2,%3},{%4,%5,%6,%7},{%8,%9},{%0,%1,%2,%3};" \
                 : "+f"((d)[0]), "+f"((d)[1]), "+f"((d)[2]), "+f"((d)[3]) \
                 : "r"((a)[0]), "r"((a)[1]), "r"((a)[2]), "r"((a)[3]), "r"(b0), "r"(b1))

extern __shared__ char smbuf[];

__global__ __launch_bounds__(128, 2)
void diffunpool_tf32_v2(const float* __restrict__ S, const float* __restrict__ X,
                        float* __restrict__ O) {
    const int nt = blockIdx.x;   // 0..1  (N tiles of 128)
    const int mt = blockIdx.y;   // 0..15 (M tiles of 128)
    const int b  = blockIdx.z;   // 0..15

    const float* Sb = S + ((size_t)b * 2048 + (size_t)mt * 128) * 256;
    const float* Xb = X + (size_t)b * 65536 + (size_t)nt * 128;
    float*       Ob = O + ((size_t)b * 2048 + (size_t)mt * 128) * 256 + (size_t)nt * 128;

    const int tid = threadIdx.x, wid = tid >> 5, lane = tid & 31;
    const int wm = (wid & 1) * 64;
    const int wn = (wid >> 1) * 64;
    const uint32_t sb = cvta_smem(smbuf);

    // ---- cp.async stage of chunk c into buffer bf (fp32, no conversion)
    auto issue = [&](int c, int bf) {
        const uint32_t abuf = sb + (uint32_t)bf * A_CHUNK_BYTES;
        const uint32_t bbuf = sb + OFF_B + (uint32_t)bf * B_CHUNK_BYTES;
#pragma unroll
        for (int q = 0; q < 8; q++) {            // A: 128 rows x 8 segs
            int flat = q * 128 + tid;
            int m = flat >> 3, seg = flat & 7;
            const float* src = Sb + (size_t)m * 256 + c * 32 + seg * 4;
            uint32_t dst = abuf + (uint32_t)m * 128 + (uint32_t)((seg ^ (m & 7)) << 4);
            CP16(dst, src);
        }
#pragma unroll
        for (int q = 0; q < 8; q++) {            // B: 32 rows x 32 segs
            int flat = q * 128 + tid;
            int k = flat >> 5, seg = flat & 31;
            const float* src = Xb + (size_t)(c * 32 + k) * 256 + seg * 4;
            uint32_t dst = bbuf + (uint32_t)k * B_ROWB + (uint32_t)(seg << 4);
            CP16(dst, src);
        }
        CPCOMMIT();
    };

    float d[4][8][4];
#pragma unroll
    for (int mf = 0; mf < 4; mf++)
#pragma unroll
        for (int j = 0; j < 8; j++)
#pragma unroll
            for (int r = 0; r < 4; r++) d[mf][j][r] = 0.0f;

    issue(0, 0);
    issue(1, 1);

    // ---- A ldmatrix lane addressing: lanes 0-7 -> rows m0..m0+7 (seg 2kk),
    // 8-15 -> m0+8..15 (seg 2kk), 16-23 -> m0..7 (seg 2kk+1), 24-31 -> m0+8..15.
    const int m_low = (lane & 7) + ((lane >> 3) & 1) * 8;
    const int halfk = lane >> 4;
    const int sw    = lane & 7;             // row XOR swizzle key (= m&7)
    // ---- B scalar lane offset: b0(kk,j) at k=8kk+(lane&3), n=wn+8j+(lane>>2)
    const uint32_t b_lane = (uint32_t)(lane & 3) * B_ROWB
                          + (uint32_t)(wn + (lane >> 2)) * 4;

    for (int c = 0; c < 8; c++) {
        CPWAIT1();                 // groups retire in order -> chunk c resident
        __syncthreads();

        const uint32_t abuf = sb + (uint32_t)(c & 1) * A_CHUNK_BYTES;
        const char*    bptr = smbuf + OFF_B + (c & 1) * B_CHUNK_BYTES + b_lane;
        const uint32_t arow = abuf + (uint32_t)(wm + m_low) * 128;

#pragma unroll
        for (int kk = 0; kk < 4; kk++) {
            uint32_t a[4][4];
#pragma unroll
            for (int mf = 0; mf < 4; mf++) {
                uint32_t addr = arow + (uint32_t)(mf * 2048)
                              + (uint32_t)(((2 * kk + halfk) ^ sw) << 4);
                LDSM4(a[mf][0], a[mf][1], a[mf][2], a[mf][3], addr);
            }
#pragma unroll
            for (int mf = 0; mf < 4; mf++)
#pragma unroll
                for (int r = 0; r < 4; r++)
                    a[mf][r] = tf32c(__uint_as_float(a[mf][r]));

            uint32_t b0[8], b1[8];
#pragma unroll
            for (int j = 0; j < 8; j++) {
                float f0 = *(const float*)(bptr + kk * (8 * B_ROWB) + j * 32);
                float f1 = *(const float*)(bptr + kk * (8 * B_ROWB) + j * 32 + 4 * B_ROWB);
                b0[j] = tf32c(f0);
                b1[j] = tf32c(f1);
            }
#pragma unroll
            for (int mf = 0; mf < 4; mf++)
#pragma unroll
                for (int j = 0; j < 8; j++)
                    MMA(d[mf][j], a[mf], b0[j], b1[j]);
        }
        __syncthreads();           // all warps done reading buffer (c&1)
        if (c < 6) issue(c + 2, c & 1);
    }

    // ---- epilogue
    const int group = lane >> 2;
    const int tcol  = (lane & 3) * 2;
#pragma unroll
    for (int mf = 0; mf < 4; mf++) {
        int m0 = wm + mf * 16 + group;
#pragma unroll
        for (int j = 0; j < 8; j++) {
            int n0 = wn + j * 8 + tcol;
            *(float2*)(Ob + (size_t)m0 * 256 + n0)       = make_float2(d[mf][j][0], d[mf][j][1]);
            *(float2*)(Ob + (size_t)(m0 + 8) * 256 + n0) = make_float2(d[mf][j][2], d[mf][j][3]);
        }
    }
}

extern "C" void kernel_launch(void* const* d_in, const int* in_sizes, int n_in,
                              void* d_out, int out_size) {
    const float* S = nullptr;
    const float* X = nullptr;
    for (int i = 0; i < n_in; i++) {
        if (in_sizes[i] == 8388608)      S = (const float*)d_in[i];
        else if (in_sizes[i] == 1048576) X = (const float*)d_in[i];
    }
    float* O = (float*)d_out;

    cudaFuncSetAttribute(diffunpool_tf32_v2,
                         cudaFuncAttributeMaxDynamicSharedMemorySize, SM_BYTES);
    dim3 grid(2, 16, 16);
    diffunpool_tf32_v2<<<grid, 128, SM_BYTES>>>(S, X, O);
}

// round 8
// speedup vs baseline: 1.9846x; 1.0063x over previous
#include <cuda_runtime.h>
#include <cstdint>

// DiffUnpool: out[b] = S[b] @ x[b]
//   S: [16, 2048, 256] f32   x: [16, 256, 256] f32   out: [16, 2048, 256] f32
// tf32 m16n8k8 (cvt.rna post-LDS), CTA 128x128, 8 warps of 64x32.
// R8 = R6 proven body with doubled warp count (64 acc/thread, occ2 ->
// 4 warps/SMSP) to hide LDS/LDSM latency. Math order identical to R6.

#define A_CHUNK_BYTES 16384          // 128 rows x 128B
#define B_ROWB 544                   // 128 floats + 32B pad
#define B_CHUNK_BYTES (32 * B_ROWB)  // 17408
#define OFF_B (2 * A_CHUNK_BYTES)
#define SM_BYTES (2 * A_CHUNK_BYTES + 2 * B_CHUNK_BYTES)  // 67584

static __device__ __forceinline__ uint32_t cvta_smem(const void* p) {
    uint32_t a;
    asm("{ .reg .u64 t; cvta.to.shared.u64 t, %1; cvt.u32.u64 %0, t; }"
        : "=r"(a) : "l"(p));
    return a;
}
static __device__ __forceinline__ uint32_t tf32c(float f) {
    uint32_t u;
    asm("cvt.rna.tf32.f32 %0, %1;" : "=r"(u) : "f"(f));
    return u;
}

#define CP16(dst, src) \
    asm volatile("cp.async.cg.shared.global [%0], [%1], 16;" :: "r"(dst), "l"(src))
#define CPCOMMIT() asm volatile("cp.async.commit_group;" ::: "memory")
#define CPWAIT1()  asm volatile("cp.async.wait_group 1;" ::: "memory")

#define LDSM4(r0, r1, r2, r3, a) \
    asm volatile("ldmatrix.sync.aligned.m8n8.x4.shared.b16 {%0,%1,%2,%3}, [%4];" \
                 : "=r"(r0), "=r"(r1), "=r"(r2), "=r"(r3) : "r"(a))

#define MMA(d, a, b0, b1) \
    asm volatile("mma.sync.aligned.m16n8k8.row.col.f32.tf32.tf32.f32 " \
                 "{%0,%1,%2,%3},{%4,%5,%6,%7},{%8,%9},{%0,%1,%2,%3};" \
                 : "+f"((d)[0]), "+f"((d)[1]), "+f"((d)[2]), "+f"((d)[3]) \
                 : "r"((a)[0]), "r"((a)[1]), "r"((a)[2]), "r"((a)[3]), "r"(b0), "r"(b1))

extern __shared__ char smbuf[];

__global__ __launch_bounds__(256, 2)
void diffunpool_tf32_v4(const float* __restrict__ S, const float* __restrict__ X,
                        float* __restrict__ O) {
    const int nt = blockIdx.x;   // 0..1
    const int mt = blockIdx.y;   // 0..15
    const int b  = blockIdx.z;   // 0..15

    const float* Sb = S + ((size_t)b * 2048 + (size_t)mt * 128) * 256;
    const float* Xb = X + (size_t)b * 65536 + (size_t)nt * 128;
    float*       Ob = O + ((size_t)b * 2048 + (size_t)mt * 128) * 256 + (size_t)nt * 128;

    const int tid = threadIdx.x, wid = tid >> 5, lane = tid & 31;
    const int wm = (wid & 1) * 64;       // 2 warp rows of 64
    const int wn = (wid >> 1) * 32;      // 4 warp cols of 32
    const uint32_t sb = cvta_smem(smbuf);

    // ---- cp.async staging of chunk c into buffer bf (256 threads, 4 segs each)
    auto issue = [&](int c, int bf) {
        const uint32_t abuf = sb + (uint32_t)bf * A_CHUNK_BYTES;
        const uint32_t bbuf = sb + OFF_B + (uint32_t)bf * B_CHUNK_BYTES;
#pragma unroll
        for (int q = 0; q < 4; q++) {            // A: 128 rows x 8 segs = 1024
            int flat = q * 256 + tid;
            int m = flat >> 3, seg = flat & 7;
            const float* src = Sb + (size_t)m * 256 + c * 32 + seg * 4;
            uint32_t dst = abuf + (uint32_t)m * 128 + (uint32_t)((seg ^ (m & 7)) << 4);
            CP16(dst, src);
        }
#pragma unroll
        for (int q = 0; q < 4; q++) {            // B: 32 rows x 32 segs = 1024
            int flat = q * 256 + tid;
            int k = flat >> 5, seg = flat & 31;
            const float* src = Xb + (size_t)(c * 32 + k) * 256 + seg * 4;
            uint32_t dst = bbuf + (uint32_t)k * B_ROWB + (uint32_t)(seg << 4);
            CP16(dst, src);
        }
        CPCOMMIT();
    };

    float d[4][4][4];
#pragma unroll
    for (int mf = 0; mf < 4; mf++)
#pragma unroll
        for (int j = 0; j < 4; j++)
#pragma unroll
            for (int r = 0; r < 4; r++) d[mf][j][r] = 0.0f;

    issue(0, 0);
    issue(1, 1);

    // ---- fragment lane addressing (validated in R6)
    const int m_low = (lane & 7) + ((lane >> 3) & 1) * 8;
    const int halfk = lane >> 4;
    const int sw    = lane & 7;
    const uint32_t b_lane = (uint32_t)(lane & 3) * B_ROWB
                          + (uint32_t)(wn + (lane >> 2)) * 4;

    for (int c = 0; c < 8; c++) {
        CPWAIT1();                 // chunk c resident (groups retire in order)
        __syncthreads();

        const uint32_t abuf = sb + (uint32_t)(c & 1) * A_CHUNK_BYTES;
        const char*    bptr = smbuf + OFF_B + (c & 1) * B_CHUNK_BYTES + b_lane;
        const uint32_t arow = abuf + (uint32_t)(wm + m_low) * 128;

#pragma unroll
        for (int kk = 0; kk < 4; kk++) {
            uint32_t a[4][4];
#pragma unroll
            for (int mf = 0; mf < 4; mf++) {
                uint32_t addr = arow + (uint32_t)(mf * 2048)
                              + (uint32_t)(((2 * kk + halfk) ^ sw) << 4);
                LDSM4(a[mf][0], a[mf][1], a[mf][2], a[mf][3], addr);
            }
#pragma unroll
            for (int mf = 0; mf < 4; mf++)
#pragma unroll
                for (int r = 0; r < 4; r++)
                    a[mf][r] = tf32c(__uint_as_float(a[mf][r]));

            uint32_t b0[4], b1[4];
#pragma unroll
            for (int j = 0; j < 4; j++) {
                float f0 = *(const float*)(bptr + kk * (8 * B_ROWB) + j * 32);
                float f1 = *(const float*)(bptr + kk * (8 * B_ROWB) + j * 32 + 4 * B_ROWB);
                b0[j] = tf32c(f0);
                b1[j] = tf32c(f1);
            }
#pragma unroll
            for (int mf = 0; mf < 4; mf++)
#pragma unroll
                for (int j = 0; j < 4; j++)
                    MMA(d[mf][j], a[mf], b0[j], b1[j]);
        }
        __syncthreads();           // all warps done reading buffer (c&1)
        if (c < 6) issue(c + 2, c & 1);
    }

    // ---- epilogue
    const int group = lane >> 2;
    const int tcol  = (lane & 3) * 2;
#pragma unroll
    for (int mf = 0; mf < 4; mf++) {
        int m0 = wm + mf * 16 + group;
#pragma unroll
        for (int j = 0; j < 4; j++) {
            int n0 = wn + j * 8 + tcol;
            *(float2*)(Ob + (size_t)m0 * 256 + n0)       = make_float2(d[mf][j][0], d[mf][j][1]);
            *(float2*)(Ob + (size_t)(m0 + 8) * 256 + n0) = make_float2(d[mf][j][2], d[mf][j][3]);
        }
    }
}

extern "C" void kernel_launch(void* const* d_in, const int* in_sizes, int n_in,
                              void* d_out, int out_size) {
    const float* S = nullptr;
    const float* X = nullptr;
    for (int i = 0; i < n_in; i++) {
        if (in_sizes[i] == 8388608)      S = (const float*)d_in[i];
        else if (in_sizes[i] == 1048576) X = (const float*)d_in[i];
    }
    float* O = (float*)d_out;

    cudaFuncSetAttribute(diffunpool_tf32_v4,
                         cudaFuncAttributeMaxDynamicSharedMemorySize, SM_BYTES);
    dim3 grid(2, 16, 16);
    diffunpool_tf32_v4<<<grid, 256, SM_BYTES>>>(S, X, O);
}